// round 3
// baseline (speedup 1.0000x reference)
#include <cuda_runtime.h>
#include <math.h>

#define BDIM   64
#define LDIM   1024
#define INDIM  512
#define HDIM   512
#define G3     1536
#define NCTA   128
#define HS     8

// ---------- static device scratch (no allocations) ----------
__device__ float g_gx[(size_t)2 * BDIM * LDIM * G3];   // [dir][b][l][1536]
__device__ float g_h[2 * 2 * HDIM * BDIM];             // [dir][buf][j][b]
__device__ unsigned g_ticket;                          // monotonic barrier counter

// =====================================================================
// Kernel 1: input projection SGEMM.  C[m,n] = sum_k X[m,k]*W[n,k] + b[n]
// X:[65536,512] W:[1536,512] both K-contiguous. 128x128 tile, Ktile=16,
// 256 threads, 8x8 per thread, double-buffered SMEM.
// =====================================================================
__global__ void __launch_bounds__(256, 2)
igemm_kernel(const float* __restrict__ X,
             const float* __restrict__ Wlr, const float* __restrict__ blr,
             const float* __restrict__ Wrl, const float* __restrict__ brl)
{
    __shared__ float As[2][16][132];
    __shared__ float Bs[2][16][132];

    const int dir = blockIdx.z;
    const float* __restrict__ W   = dir ? Wrl : Wlr;
    const float* __restrict__ bia = dir ? brl : blr;
    float* __restrict__ C = g_gx + (size_t)dir * ((size_t)BDIM * LDIM * G3);

    const int tid  = threadIdx.x;
    const int m0   = blockIdx.y * 128;
    const int n0   = blockIdx.x * 128;
    const int lrow = tid >> 2;
    const int lk   = (tid & 3) << 2;

    const float* Ap = X + (size_t)(m0 + lrow) * INDIM + lk;
    const float* Bp = W + (size_t)(n0 + lrow) * INDIM + lk;

    float4 a0r = *(const float4*)(Ap);
    float4 a1r = *(const float4*)(Ap + (size_t)64 * INDIM);
    float4 b0r = *(const float4*)(Bp);
    float4 b1r = *(const float4*)(Bp + (size_t)64 * INDIM);

    As[0][lk+0][lrow]    = a0r.x; As[0][lk+1][lrow]    = a0r.y;
    As[0][lk+2][lrow]    = a0r.z; As[0][lk+3][lrow]    = a0r.w;
    As[0][lk+0][lrow+64] = a1r.x; As[0][lk+1][lrow+64] = a1r.y;
    As[0][lk+2][lrow+64] = a1r.z; As[0][lk+3][lrow+64] = a1r.w;
    Bs[0][lk+0][lrow]    = b0r.x; Bs[0][lk+1][lrow]    = b0r.y;
    Bs[0][lk+2][lrow]    = b0r.z; Bs[0][lk+3][lrow]    = b0r.w;
    Bs[0][lk+0][lrow+64] = b1r.x; Bs[0][lk+1][lrow+64] = b1r.y;
    Bs[0][lk+2][lrow+64] = b1r.z; Bs[0][lk+3][lrow+64] = b1r.w;
    __syncthreads();

    const int tm = (tid & 15) << 2;
    const int tn = (tid >> 4) << 2;

    float acc[8][8];
    #pragma unroll
    for (int i = 0; i < 8; ++i)
        #pragma unroll
        for (int j = 0; j < 8; ++j) acc[i][j] = 0.0f;

    #pragma unroll 1
    for (int kt = 0; kt < 32; ++kt) {
        const int buf = kt & 1;
        if (kt < 31) {
            const float* Ap2 = Ap + (kt + 1) * 16;
            const float* Bp2 = Bp + (kt + 1) * 16;
            a0r = *(const float4*)(Ap2);
            a1r = *(const float4*)(Ap2 + (size_t)64 * INDIM);
            b0r = *(const float4*)(Bp2);
            b1r = *(const float4*)(Bp2 + (size_t)64 * INDIM);
        }
        #pragma unroll
        for (int k = 0; k < 16; ++k) {
            float4 xa0 = *(const float4*)&As[buf][k][tm];
            float4 xa1 = *(const float4*)&As[buf][k][tm + 64];
            float4 xb0 = *(const float4*)&Bs[buf][k][tn];
            float4 xb1 = *(const float4*)&Bs[buf][k][tn + 64];
            float am[8] = {xa0.x, xa0.y, xa0.z, xa0.w, xa1.x, xa1.y, xa1.z, xa1.w};
            float bn[8] = {xb0.x, xb0.y, xb0.z, xb0.w, xb1.x, xb1.y, xb1.z, xb1.w};
            #pragma unroll
            for (int i = 0; i < 8; ++i)
                #pragma unroll
                for (int j = 0; j < 8; ++j)
                    acc[i][j] += am[i] * bn[j];
        }
        if (kt < 31) {
            const int nb = buf ^ 1;
            As[nb][lk+0][lrow]    = a0r.x; As[nb][lk+1][lrow]    = a0r.y;
            As[nb][lk+2][lrow]    = a0r.z; As[nb][lk+3][lrow]    = a0r.w;
            As[nb][lk+0][lrow+64] = a1r.x; As[nb][lk+1][lrow+64] = a1r.y;
            As[nb][lk+2][lrow+64] = a1r.z; As[nb][lk+3][lrow+64] = a1r.w;
            Bs[nb][lk+0][lrow]    = b0r.x; Bs[nb][lk+1][lrow]    = b0r.y;
            Bs[nb][lk+2][lrow]    = b0r.z; Bs[nb][lk+3][lrow]    = b0r.w;
            Bs[nb][lk+0][lrow+64] = b1r.x; Bs[nb][lk+1][lrow+64] = b1r.y;
            Bs[nb][lk+2][lrow+64] = b1r.z; Bs[nb][lk+3][lrow+64] = b1r.w;
        }
        __syncthreads();
    }

    float bv[8];
    #pragma unroll
    for (int j = 0; j < 4; ++j) {
        bv[j]     = bia[n0 + tn + j];
        bv[4 + j] = bia[n0 + 64 + tn + j];
    }
    #pragma unroll
    for (int i = 0; i < 8; ++i) {
        const int row = m0 + ((i < 4) ? (tm + i) : (64 + tm + (i - 4)));
        float* Cp = C + (size_t)row * G3 + n0;
        float4 v0 = make_float4(acc[i][0]+bv[0], acc[i][1]+bv[1], acc[i][2]+bv[2], acc[i][3]+bv[3]);
        float4 v1 = make_float4(acc[i][4]+bv[4], acc[i][5]+bv[5], acc[i][6]+bv[6], acc[i][7]+bv[7]);
        *(float4*)(Cp + tn)      = v0;
        *(float4*)(Cp + 64 + tn) = v1;
    }
}

// =====================================================================
// Kernel 2: persistent recurrent scan. 128 CTAs (64/dir) x 256 threads.
// CTA owns HS=8 hidden units (24 W_hh rows resident in SMEM).
// Thread map: warp rg = unit, lane bg = batches {2bg, 2bg+1}.
// =====================================================================
// SMEM floats: Ws[24][512] | hs[2][128*64] | gxs[64*24] | outs[64*8]
#define SM_WS   0
#define SM_HS   12288
#define SM_GXS  28672
#define SM_OUTS 30208
#define SM_FLOATS 30720

__device__ __forceinline__ void grid_barrier()
{
    __syncthreads();
    if (threadIdx.x == 0) {
        __threadfence();
        unsigned t = atomicAdd(&g_ticket, 1u);
        unsigned target = (t / NCTA + 1u) * NCTA;
        while ((int)(*(volatile unsigned*)&g_ticket - target) < 0) { }
        __threadfence();
    }
    __syncthreads();
}

__device__ __forceinline__ float sigf(float x) { return 1.0f / (1.0f + __expf(-x)); }

__global__ void __launch_bounds__(256, 1)
scan_kernel(const float* __restrict__ feats_mask,
            const float* __restrict__ whh_lr, const float* __restrict__ bhh_lr,
            const float* __restrict__ whh_rl, const float* __restrict__ bhh_rl,
            float* __restrict__ out)
{
    extern __shared__ float sm[];
    float* Ws   = sm + SM_WS;
    float* hsS  = sm + SM_HS;
    float* gxs  = sm + SM_GXS;
    float* outs = sm + SM_OUTS;

    const int tid   = threadIdx.x;
    const int dir   = blockIdx.x >> 6;
    const int slice = blockIdx.x & 63;
    const int j0    = slice * HS;
    const int rg    = tid >> 5;
    const int bg    = tid & 31;
    const int b0    = 2 * bg;

    const float* __restrict__ whh = dir ? whh_rl : whh_lr;
    const float* __restrict__ bhh = dir ? bhh_rl : bhh_lr;
    const float* __restrict__ gxbase = g_gx + (size_t)dir * ((size_t)BDIM * LDIM * G3);
    float* __restrict__ hglob = g_h + (size_t)dir * 2 * HDIM * BDIM;

    // Ws[c][k], c = rr*3+g  (row rr of slice, gate g), contiguous in k
    for (int idx = tid; idx < 24 * 512; idx += 256) {
        const int c = idx >> 9, k = idx & 511;
        const int rr = c / 3, g = c - 3 * rr;
        Ws[c * 512 + k] = whh[(size_t)(g * HDIM + j0 + rr) * HDIM + k];
    }
    const float bh_r = bhh[j0 + rg];
    const float bh_z = bhh[HDIM + j0 + rg];
    const float bh_n = bhh[2 * HDIM + j0 + rg];

    float hp0 = 0.0f, hp1 = 0.0f;
    *(float2*)&hglob[(size_t)(j0 + rg) * BDIM + b0] = make_float2(0.0f, 0.0f);

    // constant per-thread gx addressing: e -> (batch b, gate seg, unit u)
    size_t gx_const[6]; int gx_sidx[6];
    #pragma unroll
    for (int i = 0; i < 6; ++i) {
        const int e = tid + i * 256, b = e / 24, c = e - 24 * b;
        const int seg = c >> 3, u = c & 7;
        gx_const[i] = (size_t)b * LDIM * G3 + (size_t)seg * HDIM + j0 + u;
        gx_sidx[i]  = b * 24 + u * 3 + seg;
    }
    const int    ob = tid >> 2;
    const int    ou = (tid & 3) * 2;
    const size_t out_const = (size_t)ob * LDIM * 2 * HDIM + (size_t)dir * HDIM + j0 + ou;

    grid_barrier();   // h buffer 0 fully initialized grid-wide

    for (int s = 0; s < LDIM; ++s) {
        const int cur = s & 1, nxt = cur ^ 1;
        const int t_in = dir ? (LDIM - 1 - s) : s;
        const float* __restrict__ hsrc = hglob + (size_t)cur * HDIM * BDIM;

        float gxr[6];
        #pragma unroll
        for (int i = 0; i < 6; ++i)
            gxr[i] = gxbase[gx_const[i] + (size_t)t_in * G3];

        float4 hreg[8];
        #pragma unroll
        for (int i = 0; i < 8; ++i)
            hreg[i] = *(const float4*)(hsrc + (tid + i * 256) * 4);

        #pragma unroll
        for (int i = 0; i < 6; ++i) gxs[gx_sidx[i]] = gxr[i];
        #pragma unroll
        for (int i = 0; i < 8; ++i)
            *(float4*)(hsS + (tid + i * 256) * 4) = hreg[i];
        __syncthreads();

        float ar0 = bh_r, ar1 = bh_r, az0 = bh_z, az1 = bh_z, an0 = bh_n, an1 = bh_n;

        #pragma unroll 1
        for (int c4 = 0; c4 < 4; ++c4) {
            if (c4 < 3) {
                const float* src = hsrc + (c4 + 1) * 8192;
                #pragma unroll
                for (int i = 0; i < 8; ++i)
                    hreg[i] = *(const float4*)(src + (tid + i * 256) * 4);
            }
            const float* __restrict__ hchunk = hsS + (c4 & 1) * 8192 + b0;
            const float* __restrict__ wb = Ws + (rg * 3) * 512 + c4 * 128;
            #pragma unroll 8
            for (int k = 0; k < 128; k += 4) {
                float4 wr = *(const float4*)(wb + k);
                float4 wz = *(const float4*)(wb + 512 + k);
                float4 wn = *(const float4*)(wb + 1024 + k);
                float2 h0 = *(const float2*)(hchunk + (k + 0) * 64);
                float2 h1 = *(const float2*)(hchunk + (k + 1) * 64);
                float2 h2 = *(const float2*)(hchunk + (k + 2) * 64);
                float2 h3 = *(const float2*)(hchunk + (k + 3) * 64);
                ar0 += wr.x*h0.x + wr.y*h1.x + wr.z*h2.x + wr.w*h3.x;
                ar1 += wr.x*h0.y + wr.y*h1.y + wr.z*h2.y + wr.w*h3.y;
                az0 += wz.x*h0.x + wz.y*h1.x + wz.z*h2.x + wz.w*h3.x;
                az1 += wz.x*h0.y + wz.y*h1.y + wz.z*h2.y + wz.w*h3.y;
                an0 += wn.x*h0.x + wn.y*h1.x + wn.z*h2.x + wn.w*h3.x;
                an1 += wn.x*h0.y + wn.y*h1.y + wn.z*h2.y + wn.w*h3.y;
            }
            if (c4 < 3) {
                float* dst = hsS + ((c4 + 1) & 1) * 8192;
                #pragma unroll
                for (int i = 0; i < 8; ++i)
                    *(float4*)(dst + (tid + i * 256) * 4) = hreg[i];
            }
            __syncthreads();
        }

        const float mk0 = feats_mask[(size_t)b0 * LDIM + t_in];
        const float mk1 = feats_mask[(size_t)(b0 + 1) * LDIM + t_in];
        const float* gx0 = gxs + b0 * 24 + rg * 3;
        const float* gx1 = gxs + (b0 + 1) * 24 + rg * 3;

        const float r0 = sigf(gx0[0] + ar0);
        const float z0 = sigf(gx0[1] + az0);
        const float n0v = tanhf(gx0[2] + r0 * an0);
        float hn0 = (1.0f - z0) * n0v + z0 * hp0;
        hn0 = mk0 * hn0 + (1.0f - mk0) * hp0;

        const float r1 = sigf(gx1[0] + ar1);
        const float z1 = sigf(gx1[1] + az1);
        const float n1v = tanhf(gx1[2] + r1 * an1);
        float hn1 = (1.0f - z1) * n1v + z1 * hp1;
        hn1 = mk1 * hn1 + (1.0f - mk1) * hp1;

        hp0 = hn0; hp1 = hn1;
        *(float2*)&hglob[(size_t)(nxt * HDIM + j0 + rg) * BDIM + b0] = make_float2(hn0, hn1);
        outs[b0 * 8 + rg]       = hn0;
        outs[(b0 + 1) * 8 + rg] = hn1;
        __syncthreads();

        float2 ov = *(const float2*)(outs + ob * 8 + ou);
        *(float2*)(out + out_const + (size_t)t_in * 2 * HDIM) = ov;

        grid_barrier();
    }
}

// =====================================================================
extern "C" void kernel_launch(void* const* d_in, const int* in_sizes, int n_in,
                              void* d_out, int out_size)
{
    const float* feats      = (const float*)d_in[0];
    const float* feats_mask = (const float*)d_in[1];
    const float* w_ih_lr    = (const float*)d_in[2];
    const float* w_hh_lr    = (const float*)d_in[3];
    const float* b_ih_lr    = (const float*)d_in[4];
    const float* b_hh_lr    = (const float*)d_in[5];
    const float* w_ih_rl    = (const float*)d_in[6];
    const float* w_hh_rl    = (const float*)d_in[7];
    const float* b_ih_rl    = (const float*)d_in[8];
    const float* b_hh_rl    = (const float*)d_in[9];
    float* out = (float*)d_out;

    static bool attr_set = false;
    if (!attr_set) {
        cudaFuncSetAttribute(scan_kernel, cudaFuncAttributeMaxDynamicSharedMemorySize,
                             SM_FLOATS * (int)sizeof(float));
        attr_set = true;
    }

    dim3 ggrid(G3 / 128, (BDIM * LDIM) / 128, 2);
    igemm_kernel<<<ggrid, 256>>>(feats, w_ih_lr, b_ih_lr, w_ih_rl, b_ih_rl);
    scan_kernel<<<NCTA, 256, SM_FLOATS * sizeof(float)>>>(
        feats_mask, w_hh_lr, b_hh_lr, w_hh_rl, b_hh_rl, out);
}